// round 2
// baseline (speedup 1.0000x reference)
#include <cuda_runtime.h>
#include <cuda_bf16.h>
#include <cstdint>

// Problem constants: I=16, O=8, J=4, B=16
//   n_in=1024, n_out=256, K=81 projectors but each output element is hit by
//   exactly 1-4 of them:
//
// With qr = 32*i_r + 2*j_r, qc = 32*i_c + 2*j_c  (float4 column index),
//   out[b, ij_r*4+ch, gc*4 .. +3] =
//       X4[4qr+68+ch][qc+17]                      (center, always)
//     + (i_r==i_c)            * X4[4qr+ 4+ch][qc+ 1]   (C group)
//     + (j_r==j_c)            * X4[4qr+64+ch][qc+16]   (D group)
//     + (i_r==i_c && j_r==j_c)* X4[4qr+   ch][qc+ 0]   (B group)
// where X4 is the input viewed as float4 rows of 256 quads.
//
// Each thread handles one (b, i_r, j_r, i_c, j_c) cell = 4 output rows x 1
// output quad -> 4 independent center loads (MLP>=4), up to 16 when matching.

#define N_IN   1024
#define N_OUT  256
#define BATCH  16
#define QROW   (N_IN / 4)    // 256 float4 per input row
#define OQROW  (N_OUT / 4)   // 64  float4 per output row

__global__ __launch_bounds__(128, 16)
void pool2d_density_kernel(const float* __restrict__ x, float* __restrict__ out)
{
    const int tid = threadIdx.x;
    // 2 row-groups per block: grp = b*64 + ij_r, grid = 512
    const int grp  = blockIdx.x * 2 + (tid >> 6);
    const int b    = grp >> 6;
    const int ij_r = grp & 63;
    const int i_r  = ij_r >> 3;
    const int j_r  = ij_r & 7;

    const int gc  = tid & 63;            // i_c*8 + j_c
    const int i_c = gc >> 3;
    const int j_c = gc & 7;

    const float4* __restrict__ xq =
        (const float4*)(x + (size_t)b * N_IN * N_IN);

    const int qr = 32 * i_r + 2 * j_r;   // row-group base (quad units)
    const int qc = 32 * i_c + 2 * j_c;   // col-group base (quad units)
    const int rb = 4 * qr;               // row base (row units)

    float4 acc[4];

    // center term — 4 independent loads, consecutive rows, same col quad
    #pragma unroll
    for (int ch = 0; ch < 4; ch++)
        acc[ch] = xq[(size_t)(rb + 68 + ch) * QROW + (qc + 17)];

    const bool im = (i_r == i_c);
    const bool jm = (j_r == j_c);

    if (im) {
        float4 t[4];
        #pragma unroll
        for (int ch = 0; ch < 4; ch++)
            t[ch] = xq[(size_t)(rb + 4 + ch) * QROW + (qc + 1)];
        #pragma unroll
        for (int ch = 0; ch < 4; ch++) {
            acc[ch].x += t[ch].x; acc[ch].y += t[ch].y;
            acc[ch].z += t[ch].z; acc[ch].w += t[ch].w;
        }
    }
    if (jm) {
        float4 t[4];
        #pragma unroll
        for (int ch = 0; ch < 4; ch++)
            t[ch] = xq[(size_t)(rb + 64 + ch) * QROW + (qc + 16)];
        #pragma unroll
        for (int ch = 0; ch < 4; ch++) {
            acc[ch].x += t[ch].x; acc[ch].y += t[ch].y;
            acc[ch].z += t[ch].z; acc[ch].w += t[ch].w;
        }
    }
    if (im && jm) {
        float4 t[4];
        #pragma unroll
        for (int ch = 0; ch < 4; ch++)
            t[ch] = xq[(size_t)(rb + ch) * QROW + qc];
        #pragma unroll
        for (int ch = 0; ch < 4; ch++) {
            acc[ch].x += t[ch].x; acc[ch].y += t[ch].y;
            acc[ch].z += t[ch].z; acc[ch].w += t[ch].w;
        }
    }

    float4* __restrict__ oq = (float4*)(out + (size_t)b * N_OUT * N_OUT);
    #pragma unroll
    for (int ch = 0; ch < 4; ch++)
        oq[(size_t)(ij_r * 4 + ch) * OQROW + gc] = acc[ch];
}

extern "C" void kernel_launch(void* const* d_in, const int* in_sizes, int n_in,
                              void* d_out, int out_size)
{
    const float* x = (const float*)d_in[0];   // (16, 1024, 1024) fp32
    float* out = (float*)d_out;               // (16, 256, 256) fp32

    // 512 blocks x 128 threads; each thread = one (b,i_r,j_r,i_c,j_c) cell
    // covering all 4 ch_r rows -> 4-16 independent loads in flight per thread.
    pool2d_density_kernel<<<512, 128>>>(x, out);
}